// round 4
// baseline (speedup 1.0000x reference)
#include <cuda_runtime.h>

#define F_IN 7
#define F_HID 40
#define F_OUT 3
#define KNBR 16
#define BLOCK 128
#define H_PER 5   // hidden units per lane (8 slices x 5 = 40)

// ---- f32x2 packed helpers (sm_103a) ----
__device__ __forceinline__ unsigned long long pack2(float lo, float hi) {
    unsigned long long r;
    asm("mov.b64 %0, {%1, %2};" : "=l"(r) : "f"(lo), "f"(hi));
    return r;
}
__device__ __forceinline__ unsigned long long fma2(unsigned long long a,
                                                   unsigned long long b,
                                                   unsigned long long c) {
    unsigned long long d;
    asm("fma.rn.f32x2 %0, %1, %2, %3;" : "=l"(d) : "l"(a), "l"(b), "l"(c));
    return d;
}
__device__ __forceinline__ unsigned long long add2(unsigned long long a,
                                                   unsigned long long b) {
    unsigned long long d;
    asm("add.rn.f32x2 %0, %1, %2;" : "=l"(d) : "l"(a), "l"(b));
    return d;
}
__device__ __forceinline__ void unpack2(unsigned long long v, float& lo, float& hi) {
    asm("mov.b64 {%0, %1}, %2;" : "=f"(lo), "=f"(hi) : "l"(v));
}

__global__ void __launch_bounds__(BLOCK)
aggre_mlp_kernel(const float* __restrict__ mailbox,
                 const float* __restrict__ W1,
                 const float* __restrict__ b1,
                 const float* __restrict__ W2,
                 const float* __restrict__ b2,
                 float* __restrict__ out,
                 int n_nodes, int total_warps) {
    const int lane  = threadIdx.x & 31;
    const int gwarp = (blockIdx.x * BLOCK + threadIdx.x) >> 5;
    const int sub   = lane & 3;            // which 4-message quarter
    const int h0    = (lane >> 2) * H_PER; // this lane's hidden slice

    // ---- one-time per-thread weight cache (registers only) ----
    unsigned long long wd[H_PER][8];   // [j][0..6]=W1 dup pairs, [7]=b1 dup
    unsigned long long w2p[H_PER];     // (W2[h][0], W2[h][1]) pre-scaled by 1/K
    float w2c[H_PER];                  // W2[h][2] pre-scaled by 1/K
    #pragma unroll
    for (int j = 0; j < H_PER; j++) {
        const int h = h0 + j;
        #pragma unroll
        for (int f = 0; f < F_IN; f++) {
            float w = __ldg(W1 + f * F_HID + h);
            wd[j][f] = pack2(w, w);
        }
        float bb = __ldg(b1 + h);
        wd[j][7] = pack2(bb, bb);
        const float inv = 1.0f / (float)KNBR;
        w2p[j] = pack2(__ldg(W2 + h * F_OUT + 0) * inv,
                       __ldg(W2 + h * F_OUT + 1) * inv);
        w2c[j] = __ldg(W2 + h * F_OUT + 2) * inv;
    }
    const float bias2 = (lane < F_OUT) ? __ldg(b2 + lane) : 0.0f;

    for (int node = gwarp; node < n_nodes; node += total_warps) {
        // 4 messages * 7 floats = 7 float4, contiguous & 16B aligned.
        const float4* src = reinterpret_cast<const float4*>(mailbox)
                          + node * 28 + sub * 7;
        float m[28];
        #pragma unroll
        for (int i = 0; i < 7; i++) {
            float4 v = src[i];
            m[4 * i + 0] = v.x; m[4 * i + 1] = v.y;
            m[4 * i + 2] = v.z; m[4 * i + 3] = v.w;
        }
        // pack across messages: (msg0,msg1) and (msg2,msg3)
        unsigned long long mp01[F_IN], mp23[F_IN];
        #pragma unroll
        for (int f = 0; f < F_IN; f++) {
            mp01[f] = pack2(m[f],      m[7  + f]);
            mp23[f] = pack2(m[14 + f], m[21 + f]);
        }

        unsigned long long y01 = pack2(0.f, 0.f);
        float y2 = 0.f;

        #pragma unroll
        for (int j = 0; j < H_PER; j++) {
            unsigned long long a01 = wd[j][7], a23 = wd[j][7];
            #pragma unroll
            for (int f = 0; f < F_IN; f++) {
                a01 = fma2(mp01[f], wd[j][f], a01);
                a23 = fma2(mp23[f], wd[j][f], a23);
            }
            float r0, r1, r2, r3;
            unpack2(a01, r0, r1);
            unpack2(a23, r2, r3);
            float hs = (fmaxf(r0, 0.f) + fmaxf(r1, 0.f))
                     + (fmaxf(r2, 0.f) + fmaxf(r3, 0.f));
            y01 = fma2(pack2(hs, hs), w2p[j], y01);   // y0,y1 packed
            y2  = fmaf(hs, w2c[j], y2);
        }

        // full 32-lane butterfly (sums over 4 subs x 8 slices)
        #pragma unroll
        for (int d = 16; d >= 1; d >>= 1) {
            float lo, hi;
            unpack2(y01, lo, hi);
            float lo2 = __shfl_xor_sync(0xffffffffu, lo, d);
            float hi2 = __shfl_xor_sync(0xffffffffu, hi, d);
            y01 = add2(y01, pack2(lo2, hi2));
            y2 += __shfl_xor_sync(0xffffffffu, y2, d);
        }

        if (lane < F_OUT) {
            float y0, y1;
            unpack2(y01, y0, y1);
            float v = (lane == 0) ? y0 : (lane == 1) ? y1 : y2;
            out[node * F_OUT + lane] = v + bias2;
        }
    }
}

extern "C" void kernel_launch(void* const* d_in, const int* in_sizes, int n_in,
                              void* d_out, int out_size) {
    const float* mailbox = (const float*)d_in[0];
    const float* W1      = (const float*)d_in[1];
    const float* b1      = (const float*)d_in[2];
    const float* W2      = (const float*)d_in[3];
    const float* b2      = (const float*)d_in[4];
    float* out = (float*)d_out;

    const int n_nodes = in_sizes[0] / (KNBR * F_IN);

    // Exactly-resident grid: occupancy-sized, grid-stride inside.
    int blocks_per_sm = 0;
    cudaOccupancyMaxActiveBlocksPerMultiprocessor(&blocks_per_sm,
                                                  aggre_mlp_kernel, BLOCK, 0);
    if (blocks_per_sm <= 0) blocks_per_sm = 3;
    int num_sms = 0;
    cudaDeviceGetAttribute(&num_sms, cudaDevAttrMultiProcessorCount, 0);
    if (num_sms <= 0) num_sms = 148;

    int blocks = blocks_per_sm * num_sms;
    long long max_blocks = ((long long)n_nodes * 32 + BLOCK - 1) / BLOCK;
    if ((long long)blocks > max_blocks) blocks = (int)max_blocks;
    const int total_warps = blocks * (BLOCK / 32);

    aggre_mlp_kernel<<<blocks, BLOCK>>>(mailbox, W1, b1, W2, b2, out,
                                        n_nodes, total_warps);
}

// round 5
// speedup vs baseline: 1.7375x; 1.7375x over previous
#include <cuda_runtime.h>

#define KNBR 16
#define F_IN 7
#define F_HID 40
#define F_OUT 3
#define HP (F_HID / 2)      // 20 hidden pairs
#define BLOCK 256

// ---- f32x2 packed helpers (sm_103a; ptxas never auto-fuses, must be PTX) ----
__device__ __forceinline__ unsigned long long pack2(float lo, float hi) {
    unsigned long long r;
    asm("mov.b64 %0, {%1, %2};" : "=l"(r) : "f"(lo), "f"(hi));
    return r;
}
__device__ __forceinline__ unsigned long long fma2(unsigned long long a,
                                                   unsigned long long b,
                                                   unsigned long long c) {
    unsigned long long d;
    asm("fma.rn.f32x2 %0, %1, %2, %3;" : "=l"(d) : "l"(a), "l"(b), "l"(c));
    return d;
}
__device__ __forceinline__ void unpack2(unsigned long long v, float& lo, float& hi) {
    asm("mov.b64 {%0, %1}, %2;" : "=f"(lo), "=f"(hi) : "l"(v));
}

__global__ __launch_bounds__(BLOCK, 4)   // cap at 64 regs -> 32 warps/SM
void aggre_mlp_kernel(const float* __restrict__ mailbox,
                      const float* __restrict__ W1,
                      const float* __restrict__ b1,
                      const float* __restrict__ W2,
                      const float* __restrict__ b2,
                      float* __restrict__ out,
                      int n_nodes) {
    // Per h-pair row: 16 dup-pairs [wdup(2i,0..6), bdup(2i), wdup(2i+1,0..6), bdup(2i+1)]
    // All inner-loop weight reads are broadcast LDS.64 (1 wavefront each).
    __shared__ __align__(16) float2 s_w1dup[HP][16];
    // Layer-2, packed over the h-pair: s_w2p[i][o] = (W2[2i][o], W2[2i+1][o]) / K
    __shared__ __align__(16) float2 s_w2p[HP][3];
    __shared__ float s_b2[F_OUT];

    const int tid = threadIdx.x;
    for (int i = tid; i < HP * 16; i += BLOCK) {
        int p = i >> 4, s = i & 15;          // pair p, slot s
        int h = 2 * p + (s >> 3);            // which h of the pair
        int f = s & 7;                       // 0..6 weight, 7 bias
        float v = (f < F_IN) ? W1[f * F_HID + h] : b1[h];
        s_w1dup[p][s] = make_float2(v, v);
    }
    for (int i = tid; i < HP * 3; i += BLOCK) {
        int p = i / 3, o = i % 3;
        const float inv = 1.0f / (float)KNBR;
        s_w2p[p][o] = make_float2(W2[(2 * p) * F_OUT + o] * inv,
                                  W2[(2 * p + 1) * F_OUT + o] * inv);
    }
    if (tid < F_OUT) s_b2[tid] = b2[tid];
    __syncthreads();

    const long long gt = (long long)blockIdx.x * BLOCK + tid;
    if (gt >= (long long)n_nodes * 4) return;

    const long long node = gt >> 2;          // 4 threads per node
    const int sub = (int)(gt & 3);

    // 4 messages * 7 floats = 7 float4, contiguous & 16B aligned.
    const float4* src = reinterpret_cast<const float4*>(mailbox) + node * 28 + sub * 7;
    float m[28];
    #pragma unroll
    for (int i = 0; i < 7; i++) {
        float4 v = src[i];
        m[4 * i + 0] = v.x; m[4 * i + 1] = v.y;
        m[4 * i + 2] = v.z; m[4 * i + 3] = v.w;
    }
    // Pack across messages (plain storage, 28 regs total).
    unsigned long long mp01[F_IN], mp23[F_IN];
    #pragma unroll
    for (int f = 0; f < F_IN; f++) {
        mp01[f] = pack2(m[f],      m[7  + f]);
        mp23[f] = pack2(m[14 + f], m[21 + f]);
    }

    // Output accumulators, packed over (even h, odd h).
    unsigned long long y0p = pack2(0.f, 0.f);
    unsigned long long y1p = pack2(0.f, 0.f);
    unsigned long long y2p = pack2(0.f, 0.f);

    #pragma unroll 2
    for (int p = 0; p < HP; p++) {
        const unsigned long long* wr =
            reinterpret_cast<const unsigned long long*>(&s_w1dup[p][0]);

        // ---- h = 2p (even) ----
        unsigned long long bA = wr[7];
        unsigned long long a01 = bA, a23 = bA;
        #pragma unroll
        for (int f = 0; f < F_IN; f++) {
            unsigned long long w = wr[f];
            a01 = fma2(mp01[f], w, a01);
            a23 = fma2(mp23[f], w, a23);
        }
        float r0, r1, r2, r3;
        unpack2(a01, r0, r1); unpack2(a23, r2, r3);
        float hsA = (fmaxf(r0, 0.f) + fmaxf(r1, 0.f))
                  + (fmaxf(r2, 0.f) + fmaxf(r3, 0.f));

        // ---- h = 2p+1 (odd) ----
        unsigned long long bB = wr[15];
        unsigned long long b01 = bB, b23 = bB;
        #pragma unroll
        for (int f = 0; f < F_IN; f++) {
            unsigned long long w = wr[8 + f];
            b01 = fma2(mp01[f], w, b01);
            b23 = fma2(mp23[f], w, b23);
        }
        unpack2(b01, r0, r1); unpack2(b23, r2, r3);
        float hsB = (fmaxf(r0, 0.f) + fmaxf(r1, 0.f))
                  + (fmaxf(r2, 0.f) + fmaxf(r3, 0.f));

        // ---- layer 2, packed over the h-pair ----
        unsigned long long hs2 = pack2(hsA, hsB);
        const unsigned long long* w2r =
            reinterpret_cast<const unsigned long long*>(&s_w2p[p][0]);
        y0p = fma2(hs2, w2r[0], y0p);
        y1p = fma2(hs2, w2r[1], y1p);
        y2p = fma2(hs2, w2r[2], y2p);
    }

    float e, o;
    unpack2(y0p, e, o); float y0 = e + o;
    unpack2(y1p, e, o); float y1 = e + o;
    unpack2(y2p, e, o); float y2 = e + o;

    // Reduce over the 4 sibling lanes (adjacent lanes, xor 1 then 2).
    #pragma unroll
    for (int d = 1; d < 4; d <<= 1) {
        y0 += __shfl_xor_sync(0xffffffffu, y0, d);
        y1 += __shfl_xor_sync(0xffffffffu, y1, d);
        y2 += __shfl_xor_sync(0xffffffffu, y2, d);
    }

    if (sub < F_OUT) {
        float v = (sub == 0) ? y0 : (sub == 1) ? y1 : y2;
        out[node * F_OUT + sub] = v + s_b2[sub];
    }
}

extern "C" void kernel_launch(void* const* d_in, const int* in_sizes, int n_in,
                              void* d_out, int out_size) {
    const float* mailbox = (const float*)d_in[0];
    const float* W1      = (const float*)d_in[1];
    const float* b1      = (const float*)d_in[2];
    const float* W2      = (const float*)d_in[3];
    const float* b2      = (const float*)d_in[4];
    float* out = (float*)d_out;

    const int n_nodes = in_sizes[0] / (KNBR * F_IN);
    const long long total_threads = (long long)n_nodes * 4;
    const int blocks = (int)((total_threads + BLOCK - 1) / BLOCK);

    aggre_mlp_kernel<<<blocks, BLOCK>>>(mailbox, W1, b1, W2, b2, out, n_nodes);
}

// round 6
// speedup vs baseline: 2.1408x; 1.2321x over previous
#include <cuda_runtime.h>

#define KNBR 16
#define F_IN 7
#define F_HID 40
#define F_OUT 3
#define HP (F_HID / 2)      // 20 hidden pairs
#define BLOCK 128

typedef unsigned long long u64;

// ---- f32x2 packed helpers (sm_103a; ptxas never auto-fuses, must be PTX) ----
__device__ __forceinline__ u64 pack2(float lo, float hi) {
    u64 r;
    asm("mov.b64 %0, {%1, %2};" : "=l"(r) : "f"(lo), "f"(hi));
    return r;
}
__device__ __forceinline__ u64 fma2(u64 a, u64 b, u64 c) {
    u64 d;
    asm("fma.rn.f32x2 %0, %1, %2, %3;" : "=l"(d) : "l"(a), "l"(b), "l"(c));
    return d;
}
__device__ __forceinline__ u64 add2(u64 a, u64 b) {
    u64 d;
    asm("add.rn.f32x2 %0, %1, %2;" : "=l"(d) : "l"(a), "l"(b));
    return d;
}
__device__ __forceinline__ void unpack2(u64 v, float& lo, float& hi) {
    asm("mov.b64 {%0, %1}, %2;" : "=f"(lo), "=f"(hi) : "l"(v));
}
__device__ __forceinline__ u64 relu2(u64 v) {
    float lo, hi;
    unpack2(v, lo, hi);
    return pack2(fmaxf(lo, 0.f), fmaxf(hi, 0.f));   // 2x FMNMX (alu pipe)
}

__global__ __launch_bounds__(BLOCK, 6)   // ~85-reg cap -> 24 warps/SM
void aggre_mlp_kernel(const float* __restrict__ mailbox,
                      const float* __restrict__ W1,
                      const float* __restrict__ b1,
                      const float* __restrict__ W2,
                      const float* __restrict__ b2,
                      float* __restrict__ out,
                      int n_nodes) {
    // Natural h-pair weights (NO duplication -> minimal LDS traffic):
    //   s_w1p[p][f] = (W1[f][2p], W1[f][2p+1]), f<7;  [7] = (b1[2p], b1[2p+1])
    __shared__ __align__(16) float2 s_w1p[HP][8];
    //   s_w2p[p][o] = (W2[2p][o], W2[2p+1][o]) / K
    __shared__ __align__(8)  float2 s_w2p[HP][3];
    __shared__ float s_b2[F_OUT];

    const int tid = threadIdx.x;
    for (int i = tid; i < HP * 8; i += BLOCK) {
        int p = i >> 3, f = i & 7;
        float lo, hi;
        if (f < F_IN) { lo = W1[f * F_HID + 2 * p]; hi = W1[f * F_HID + 2 * p + 1]; }
        else          { lo = b1[2 * p];             hi = b1[2 * p + 1]; }
        s_w1p[p][f] = make_float2(lo, hi);
    }
    const float inv = 1.0f / (float)KNBR;
    for (int i = tid; i < HP * 3; i += BLOCK) {
        int p = i / 3, o = i % 3;
        s_w2p[p][o] = make_float2(W2[(2 * p) * F_OUT + o] * inv,
                                  W2[(2 * p + 1) * F_OUT + o] * inv);
    }
    if (tid < F_OUT) s_b2[tid] = b2[tid];
    __syncthreads();

    const long long gt = (long long)blockIdx.x * BLOCK + tid;
    if (gt >= (long long)n_nodes * 4) return;

    const long long node = gt >> 2;          // 4 threads per node
    const int sub = (int)(gt & 3);

    // 4 messages * 7 floats = 7 float4, contiguous & 16B aligned.
    const float4* src = reinterpret_cast<const float4*>(mailbox) + node * 28 + sub * 7;
    float m[28];
    #pragma unroll
    for (int i = 0; i < 7; i++) {
        float4 v = src[i];
        m[4 * i + 0] = v.x; m[4 * i + 1] = v.y;
        m[4 * i + 2] = v.z; m[4 * i + 3] = v.w;
    }
    // Duplicate each message scalar into both f32x2 halves (operand-a).
    u64 md[28];
    #pragma unroll
    for (int i = 0; i < 28; i++) md[i] = pack2(m[i], m[i]);

    // Output accumulators, packed over (even h, odd h).
    u64 y0p = pack2(0.f, 0.f);
    u64 y1p = pack2(0.f, 0.f);
    u64 y2p = pack2(0.f, 0.f);

    #pragma unroll 2
    for (int p = 0; p < HP; p++) {
        const u64* wr = reinterpret_cast<const u64*>(&s_w1p[p][0]);
        const u64 bp = wr[7];
        u64 a0 = bp, a1 = bp, a2 = bp, a3 = bp;   // 4 independent chains
        #pragma unroll
        for (int f = 0; f < F_IN; f++) {
            const u64 w = wr[f];                  // broadcast LDS.64 (natural pair)
            a0 = fma2(md[f],      w, a0);
            a1 = fma2(md[7  + f], w, a1);
            a2 = fma2(md[14 + f], w, a2);
            a3 = fma2(md[21 + f], w, a3);
        }
        // relu (alu pipe) + packed sum over 4 messages (3 add2)
        const u64 hs2 = add2(add2(relu2(a0), relu2(a1)),
                             add2(relu2(a2), relu2(a3)));
        // layer 2 folded through mean, packed over the h-pair
        const u64* w2r = reinterpret_cast<const u64*>(&s_w2p[p][0]);
        y0p = fma2(hs2, w2r[0], y0p);
        y1p = fma2(hs2, w2r[1], y1p);
        y2p = fma2(hs2, w2r[2], y2p);
    }

    float e, o;
    unpack2(y0p, e, o); float y0 = e + o;
    unpack2(y1p, e, o); float y1 = e + o;
    unpack2(y2p, e, o); float y2 = e + o;

    // Reduce over the 4 sibling lanes (adjacent lanes: xor 1, then 2).
    #pragma unroll
    for (int d = 1; d < 4; d <<= 1) {
        y0 += __shfl_xor_sync(0xffffffffu, y0, d);
        y1 += __shfl_xor_sync(0xffffffffu, y1, d);
        y2 += __shfl_xor_sync(0xffffffffu, y2, d);
    }

    if (sub < F_OUT) {
        float v = (sub == 0) ? y0 : (sub == 1) ? y1 : y2;
        out[node * F_OUT + sub] = v + s_b2[sub];
    }
}

extern "C" void kernel_launch(void* const* d_in, const int* in_sizes, int n_in,
                              void* d_out, int out_size) {
    const float* mailbox = (const float*)d_in[0];
    const float* W1      = (const float*)d_in[1];
    const float* b1      = (const float*)d_in[2];
    const float* W2      = (const float*)d_in[3];
    const float* b2      = (const float*)d_in[4];
    float* out = (float*)d_out;

    const int n_nodes = in_sizes[0] / (KNBR * F_IN);
    const long long total_threads = (long long)n_nodes * 4;
    const int blocks = (int)((total_threads + BLOCK - 1) / BLOCK);

    aggre_mlp_kernel<<<blocks, BLOCK>>>(mailbox, W1, b1, W2, b2, out, n_nodes);
}

// round 7
// speedup vs baseline: 2.3057x; 1.0770x over previous
#include <cuda_runtime.h>

#define KNBR 16
#define F_IN 7
#define F_HID 40
#define F_OUT 3
#define HP (F_HID / 2)      // 20 hidden pairs
#define BLOCK 128

typedef unsigned long long u64;

// Weights in constant memory: warp-uniform reads ride the uniform-const port
// (LDCU), NOT L1tex -> removes the dominant LDS wavefront traffic.
__constant__ __align__(16) float cW1[F_IN * F_HID];
__constant__ __align__(16) float cb1[F_HID];
__constant__ __align__(16) float cW2[F_HID * F_OUT];
__constant__ __align__(16) float cb2[F_OUT];

// ---- f32x2 packed helpers (sm_103a; ptxas never auto-fuses, must be PTX) ----
__device__ __forceinline__ u64 pack2(float lo, float hi) {
    u64 r;
    asm("mov.b64 %0, {%1, %2};" : "=l"(r) : "f"(lo), "f"(hi));
    return r;
}
__device__ __forceinline__ u64 fma2(u64 a, u64 b, u64 c) {
    u64 d;
    asm("fma.rn.f32x2 %0, %1, %2, %3;" : "=l"(d) : "l"(a), "l"(b), "l"(c));
    return d;
}
__device__ __forceinline__ u64 add2(u64 a, u64 b) {
    u64 d;
    asm("add.rn.f32x2 %0, %1, %2;" : "=l"(d) : "l"(a), "l"(b));
    return d;
}
__device__ __forceinline__ void unpack2(u64 v, float& lo, float& hi) {
    asm("mov.b64 {%0, %1}, %2;" : "=f"(lo), "=f"(hi) : "l"(v));
}
__device__ __forceinline__ u64 relu2(u64 v) {
    float lo, hi;
    unpack2(v, lo, hi);
    return pack2(fmaxf(lo, 0.f), fmaxf(hi, 0.f));   // 2x FMNMX (alu pipe)
}

__global__ __launch_bounds__(BLOCK, 6)
void aggre_mlp_kernel(const float* __restrict__ mailbox,
                      float* __restrict__ out,
                      int n_nodes) {
    // Only W2 needs repacking (stride-3 gather) -> tiny smem table.
    //   s_w2p[p][o] = (W2[2p][o], W2[2p+1][o]) / K
    __shared__ __align__(8) float2 s_w2p[HP][3];
    __shared__ float s_b2[F_OUT];

    const int tid = threadIdx.x;
    if (tid < HP * 3) {
        int p = tid / 3, o = tid % 3;
        const float inv = 1.0f / (float)KNBR;
        s_w2p[p][o] = make_float2(cW2[(2 * p) * F_OUT + o] * inv,
                                  cW2[(2 * p + 1) * F_OUT + o] * inv);
    }
    if (tid < F_OUT) s_b2[tid] = cb2[tid];
    __syncthreads();

    const long long gt = (long long)blockIdx.x * BLOCK + tid;
    if (gt >= (long long)n_nodes * 4) return;

    const long long node = gt >> 2;          // 4 threads per node
    const int sub = (int)(gt & 3);

    // 4 messages * 7 floats = 7 float4, contiguous & 16B aligned.
    const float4* src = reinterpret_cast<const float4*>(mailbox) + node * 28 + sub * 7;
    float m[28];
    #pragma unroll
    for (int i = 0; i < 7; i++) {
        float4 v = src[i];
        m[4 * i + 0] = v.x; m[4 * i + 1] = v.y;
        m[4 * i + 2] = v.z; m[4 * i + 3] = v.w;
    }
    // Duplicate each message scalar into both f32x2 halves (operand-a).
    u64 md[28];
    #pragma unroll
    for (int i = 0; i < 28; i++) md[i] = pack2(m[i], m[i]);

    // Output accumulators, packed over (even h, odd h).
    u64 y0p = pack2(0.f, 0.f);
    u64 y1p = pack2(0.f, 0.f);
    u64 y2p = pack2(0.f, 0.f);

    #pragma unroll
    for (int p = 0; p < HP; p++) {
        // Natural h-pair weights straight from constant memory (adjacent in
        // row-major W1) -> LDCU.64 with immediate offsets, zero L1tex traffic.
        const u64 bp = *reinterpret_cast<const u64*>(&cb1[2 * p]);
        u64 a0 = bp, a1 = bp, a2 = bp, a3 = bp;   // 4 independent chains
        #pragma unroll
        for (int f = 0; f < F_IN; f++) {
            const u64 w = *reinterpret_cast<const u64*>(&cW1[f * F_HID + 2 * p]);
            a0 = fma2(md[f],      w, a0);
            a1 = fma2(md[7  + f], w, a1);
            a2 = fma2(md[14 + f], w, a2);
            a3 = fma2(md[21 + f], w, a3);
        }
        // relu (alu pipe) + packed sum over 4 messages (3 add2)
        const u64 hs2 = add2(add2(relu2(a0), relu2(a1)),
                             add2(relu2(a2), relu2(a3)));
        // layer 2 folded through mean, packed over the h-pair
        const u64* w2r = reinterpret_cast<const u64*>(&s_w2p[p][0]);
        y0p = fma2(hs2, w2r[0], y0p);
        y1p = fma2(hs2, w2r[1], y1p);
        y2p = fma2(hs2, w2r[2], y2p);
    }

    float e, o;
    unpack2(y0p, e, o); float y0 = e + o;
    unpack2(y1p, e, o); float y1 = e + o;
    unpack2(y2p, e, o); float y2 = e + o;

    // Reduce over the 4 sibling lanes (adjacent lanes: xor 1, then 2).
    #pragma unroll
    for (int d = 1; d < 4; d <<= 1) {
        y0 += __shfl_xor_sync(0xffffffffu, y0, d);
        y1 += __shfl_xor_sync(0xffffffffu, y1, d);
        y2 += __shfl_xor_sync(0xffffffffu, y2, d);
    }

    if (sub < F_OUT) {
        float v = (sub == 0) ? y0 : (sub == 1) ? y1 : y2;
        out[node * F_OUT + sub] = v + s_b2[sub];
    }
}

extern "C" void kernel_launch(void* const* d_in, const int* in_sizes, int n_in,
                              void* d_out, int out_size) {
    const float* mailbox = (const float*)d_in[0];
    float* out = (float*)d_out;

    // Stage weights into constant memory (async D2D -> graph-capturable).
    cudaMemcpyToSymbolAsync(cW1, d_in[1], F_IN * F_HID * sizeof(float), 0,
                            cudaMemcpyDeviceToDevice, 0);
    cudaMemcpyToSymbolAsync(cb1, d_in[2], F_HID * sizeof(float), 0,
                            cudaMemcpyDeviceToDevice, 0);
    cudaMemcpyToSymbolAsync(cW2, d_in[3], F_HID * F_OUT * sizeof(float), 0,
                            cudaMemcpyDeviceToDevice, 0);
    cudaMemcpyToSymbolAsync(cb2, d_in[4], F_OUT * sizeof(float), 0,
                            cudaMemcpyDeviceToDevice, 0);

    const int n_nodes = in_sizes[0] / (KNBR * F_IN);
    const long long total_threads = (long long)n_nodes * 4;
    const int blocks = (int)((total_threads + BLOCK - 1) / BLOCK);

    aggre_mlp_kernel<<<blocks, BLOCK>>>(mailbox, out, n_nodes);
}

// round 8
// speedup vs baseline: 2.4032x; 1.0423x over previous
#include <cuda_runtime.h>

#define KNBR 16
#define F_IN 7
#define F_HID 40
#define F_OUT 3
#define HP (F_HID / 2)      // 20 hidden pairs
#define BLOCK 128

// Combined constant layout: W1[0..279] | b1[280..319] | W2[320..439] | b2[440..442]
#define OFF_W1 0
#define OFF_B1 280
#define OFF_W2 320
#define OFF_B2 440
#define W_TOTAL 444         // padded to even

typedef unsigned long long u64;

__constant__ __align__(16) float cAll[W_TOTAL];
__device__   __align__(16) float g_stage[W_TOTAL];

// ---- f32x2 packed helpers (sm_103a; ptxas never auto-fuses, must be PTX) ----
__device__ __forceinline__ u64 pack2(float lo, float hi) {
    u64 r;
    asm("mov.b64 %0, {%1, %2};" : "=l"(r) : "f"(lo), "f"(hi));
    return r;
}
__device__ __forceinline__ u64 fma2(u64 a, u64 b, u64 c) {
    u64 d;
    asm("fma.rn.f32x2 %0, %1, %2, %3;" : "=l"(d) : "l"(a), "l"(b), "l"(c));
    return d;
}
__device__ __forceinline__ u64 add2(u64 a, u64 b) {
    u64 d;
    asm("add.rn.f32x2 %0, %1, %2;" : "=l"(d) : "l"(a), "l"(b));
    return d;
}
__device__ __forceinline__ void unpack2(u64 v, float& lo, float& hi) {
    asm("mov.b64 {%0, %1}, %2;" : "=f"(lo), "=f"(hi) : "l"(v));
}
__device__ __forceinline__ u64 relu2(u64 v) {
    float lo, hi;
    unpack2(v, lo, hi);
    return pack2(fmaxf(lo, 0.f), fmaxf(hi, 0.f));   // 2x FMNMX (alu pipe)
}

// Pack all weights into one contiguous staging buffer (1 graph node).
__global__ void gather_weights(const float* __restrict__ W1,
                               const float* __restrict__ b1,
                               const float* __restrict__ W2,
                               const float* __restrict__ b2) {
    int i = threadIdx.x;
    if (i < 280)      g_stage[OFF_W1 + i]       = W1[i];
    else if (i < 320) g_stage[OFF_B1 + i - 280] = b1[i - 280];
    else if (i < 440) g_stage[OFF_W2 + i - 320] = W2[i - 320];
    else if (i < 443) g_stage[OFF_B2 + i - 440] = b2[i - 440];
}

__global__ __launch_bounds__(BLOCK, 6)
void aggre_mlp_kernel(const float* __restrict__ mailbox,
                      float* __restrict__ out,
                      int n_nodes) {
    // Only W2 needs repacking (stride-3 gather) -> tiny smem table.
    //   s_w2p[p][o] = (W2[2p][o], W2[2p+1][o]) / K
    __shared__ __align__(8) float2 s_w2p[HP][3];
    __shared__ float s_b2[F_OUT];

    const int tid = threadIdx.x;
    if (tid < HP * 3) {
        int p = tid / 3, o = tid % 3;
        const float inv = 1.0f / (float)KNBR;
        s_w2p[p][o] = make_float2(cAll[OFF_W2 + (2 * p) * F_OUT + o] * inv,
                                  cAll[OFF_W2 + (2 * p + 1) * F_OUT + o] * inv);
    }
    if (tid < F_OUT) s_b2[tid] = cAll[OFF_B2 + tid];
    __syncthreads();

    const long long gt = (long long)blockIdx.x * BLOCK + tid;
    if (gt >= (long long)n_nodes * 4) return;

    const long long node = gt >> 2;          // 4 threads per node
    const int sub = (int)(gt & 3);

    // 4 messages * 7 floats = 7 float4, contiguous & 16B aligned.
    const float4* src = reinterpret_cast<const float4*>(mailbox) + node * 28 + sub * 7;
    // Duplicate each message scalar into both f32x2 halves (operand-a).
    u64 md[28];
    #pragma unroll
    for (int i = 0; i < 7; i++) {
        float4 v = src[i];
        md[4 * i + 0] = pack2(v.x, v.x);
        md[4 * i + 1] = pack2(v.y, v.y);
        md[4 * i + 2] = pack2(v.z, v.z);
        md[4 * i + 3] = pack2(v.w, v.w);
    }

    // Output accumulators, packed over (even h, odd h).
    u64 y0p = pack2(0.f, 0.f);
    u64 y1p = pack2(0.f, 0.f);
    u64 y2p = pack2(0.f, 0.f);

    #pragma unroll
    for (int p = 0; p < HP; p++) {
        // Natural h-pair weights straight from constant memory (adjacent in
        // row-major W1) -> uniform-const port, zero L1tex traffic.
        const u64 bp = *reinterpret_cast<const u64*>(&cAll[OFF_B1 + 2 * p]);
        u64 a0 = bp, a1 = bp, a2 = bp, a3 = bp;   // 4 independent chains
        #pragma unroll
        for (int f = 0; f < F_IN; f++) {
            const u64 w = *reinterpret_cast<const u64*>(
                &cAll[OFF_W1 + f * F_HID + 2 * p]);
            a0 = fma2(md[f],      w, a0);
            a1 = fma2(md[7  + f], w, a1);
            a2 = fma2(md[14 + f], w, a2);
            a3 = fma2(md[21 + f], w, a3);
        }
        // relu (alu pipe) + packed sum over 4 messages (3 add2)
        const u64 hs2 = add2(add2(relu2(a0), relu2(a1)),
                             add2(relu2(a2), relu2(a3)));
        // layer 2 folded through mean, packed over the h-pair
        const u64* w2r = reinterpret_cast<const u64*>(&s_w2p[p][0]);
        y0p = fma2(hs2, w2r[0], y0p);
        y1p = fma2(hs2, w2r[1], y1p);
        y2p = fma2(hs2, w2r[2], y2p);
    }

    float e, o;
    unpack2(y0p, e, o); float y0 = e + o;
    unpack2(y1p, e, o); float y1 = e + o;
    unpack2(y2p, e, o); float y2 = e + o;

    // Reduce over the 4 sibling lanes (adjacent lanes: xor 1, then 2).
    #pragma unroll
    for (int d = 1; d < 4; d <<= 1) {
        y0 += __shfl_xor_sync(0xffffffffu, y0, d);
        y1 += __shfl_xor_sync(0xffffffffu, y1, d);
        y2 += __shfl_xor_sync(0xffffffffu, y2, d);
    }

    if (sub < F_OUT) {
        float v = (sub == 0) ? y0 : (sub == 1) ? y1 : y2;
        out[node * F_OUT + sub] = v + s_b2[sub];
    }
}

extern "C" void kernel_launch(void* const* d_in, const int* in_sizes, int n_in,
                              void* d_out, int out_size) {
    const float* mailbox = (const float*)d_in[0];
    float* out = (float*)d_out;

    // 1) Pack weights into contiguous device staging (kernel node).
    gather_weights<<<1, 512>>>((const float*)d_in[1], (const float*)d_in[2],
                               (const float*)d_in[3], (const float*)d_in[4]);
    // 2) Single D2D copy into constant memory (graph-capturable).
    void* stage_ptr = nullptr;
    cudaGetSymbolAddress(&stage_ptr, g_stage);
    cudaMemcpyToSymbolAsync(cAll, stage_ptr, W_TOTAL * sizeof(float), 0,
                            cudaMemcpyDeviceToDevice, 0);

    const int n_nodes = in_sizes[0] / (KNBR * F_IN);
    const long long total_threads = (long long)n_nodes * 4;
    const int blocks = (int)((total_threads + BLOCK - 1) / BLOCK);

    aggre_mlp_kernel<<<blocks, BLOCK>>>(mailbox, out, n_nodes);
}

// round 9
// speedup vs baseline: 2.5852x; 1.0758x over previous
#include <cuda_runtime.h>

#define KNBR 16
#define F_IN 7
#define F_HID 40
#define F_OUT 3
#define HP (F_HID / 2)      // 20 hidden pairs
#define BLOCK 128

// Combined constant layout (all 16B-aligned blocks):
//   W1[0..279]  row-major f*40+h
//   b1[280..319]
//   W2P[320..439]  packed h-pair layout, pre-scaled by 1/K:
//     for p: 6 floats = (W2[2p][0],W2[2p+1][0], W2[2p][1],W2[2p+1][1], W2[2p][2],W2[2p+1][2])
//   b2[440..442]
#define OFF_W1 0
#define OFF_B1 280
#define OFF_W2P 320
#define OFF_B2 440
#define W_TOTAL 444

typedef unsigned long long u64;

__constant__ __align__(16) float cAll[W_TOTAL];
__device__   __align__(16) float g_stage[W_TOTAL];

// ---- f32x2 packed helpers (sm_103a) ----
__device__ __forceinline__ u64 pack2(float lo, float hi) {
    u64 r;
    asm("mov.b64 %0, {%1, %2};" : "=l"(r) : "f"(lo), "f"(hi));
    return r;
}
__device__ __forceinline__ u64 fma2(u64 a, u64 b, u64 c) {
    u64 d;
    asm("fma.rn.f32x2 %0, %1, %2, %3;" : "=l"(d) : "l"(a), "l"(b), "l"(c));
    return d;
}
__device__ __forceinline__ u64 add2(u64 a, u64 b) {
    u64 d;
    asm("add.rn.f32x2 %0, %1, %2;" : "=l"(d) : "l"(a), "l"(b));
    return d;
}
__device__ __forceinline__ void unpack2(u64 v, float& lo, float& hi) {
    asm("mov.b64 {%0, %1}, %2;" : "=f"(lo), "=f"(hi) : "l"(v));
}
__device__ __forceinline__ u64 relu2(u64 v) {
    float lo, hi;
    unpack2(v, lo, hi);
    return pack2(fmaxf(lo, 0.f), fmaxf(hi, 0.f));   // FMNMX on alu pipe
}
__device__ __forceinline__ u64 f4lo(const float4& v) { return pack2(v.x, v.y); }
__device__ __forceinline__ u64 f4hi(const float4& v) { return pack2(v.z, v.w); }

// Pack all weights into one contiguous staging buffer (1 graph node).
__global__ void gather_weights(const float* __restrict__ W1,
                               const float* __restrict__ b1,
                               const float* __restrict__ W2,
                               const float* __restrict__ b2) {
    int i = threadIdx.x;
    if (i < 280)      g_stage[OFF_W1 + i]       = W1[i];
    else if (i < 320) g_stage[OFF_B1 + i - 280] = b1[i - 280];
    else if (i < 440) {
        int j = i - 320;                 // packed W2P index
        int p = j / 6, s = j % 6;        // pair p, slot s
        int o = s >> 1;                  // output index
        int h = 2 * p + (s & 1);         // which h of the pair
        g_stage[OFF_W2P + j] = W2[h * F_OUT + o] * (1.0f / (float)KNBR);
    }
    else if (i < 443) g_stage[OFF_B2 + i - 440] = b2[i - 440];
}

__global__ __launch_bounds__(BLOCK, 6)
void aggre_mlp_kernel(const float* __restrict__ mailbox,
                      float* __restrict__ out,
                      int n_nodes) {
    const int tid = threadIdx.x;
    const long long gt = (long long)blockIdx.x * BLOCK + tid;
    if (gt >= (long long)n_nodes * 4) return;

    const long long node = gt >> 2;          // 4 threads per node
    const int sub = (int)(gt & 3);

    // 4 messages * 7 floats = 7 float4, contiguous & 16B aligned.
    const float4* src = reinterpret_cast<const float4*>(mailbox) + node * 28 + sub * 7;
    // Duplicate each message scalar into both f32x2 halves (operand-a).
    u64 md[28];
    #pragma unroll
    for (int i = 0; i < 7; i++) {
        float4 v = src[i];
        md[4 * i + 0] = pack2(v.x, v.x);
        md[4 * i + 1] = pack2(v.y, v.y);
        md[4 * i + 2] = pack2(v.z, v.z);
        md[4 * i + 3] = pack2(v.w, v.w);
    }

    // Output accumulators, packed over (even h, odd h) of each pair.
    u64 y0p = pack2(0.f, 0.f);
    u64 y1p = pack2(0.f, 0.f);
    u64 y2p = pack2(0.f, 0.f);

    const float4* cW1q = reinterpret_cast<const float4*>(&cAll[OFF_W1]);  // stride 10 per f
    const float4* cB1q = reinterpret_cast<const float4*>(&cAll[OFF_B1]);
    const float4* cW2q = reinterpret_cast<const float4*>(&cAll[OFF_W2P]);

    // Process 2 h-pairs (4 hidden units) per iteration -> wide LDC.128 const
    // reads (11 per block vs 22 narrow), staying under the const-port floor.
    #pragma unroll
    for (int j = 0; j < HP / 2; j++) {       // j-th 4-h block: pairs 2j, 2j+1
        const float4 bq = cB1q[j];           // b1[4j..4j+3]
        const u64 bpA = f4lo(bq), bpB = f4hi(bq);
        u64 a0 = bpA, a1 = bpA, a2 = bpA, a3 = bpA;   // pair A chains
        u64 c0 = bpB, c1 = bpB, c2 = bpB, c3 = bpB;   // pair B chains
        #pragma unroll
        for (int f = 0; f < F_IN; f++) {
            const float4 wq = cW1q[f * 10 + j];       // W1[f][4j..4j+3]
            const u64 wA = f4lo(wq), wB = f4hi(wq);
            a0 = fma2(md[f],      wA, a0);  c0 = fma2(md[f],      wB, c0);
            a1 = fma2(md[7  + f], wA, a1);  c1 = fma2(md[7  + f], wB, c1);
            a2 = fma2(md[14 + f], wA, a2);  c2 = fma2(md[14 + f], wB, c2);
            a3 = fma2(md[21 + f], wA, a3);  c3 = fma2(md[21 + f], wB, c3);
        }
        // relu (alu pipe) + packed sum over 4 messages (3 add2 per pair)
        const u64 hsA = add2(add2(relu2(a0), relu2(a1)),
                             add2(relu2(a2), relu2(a3)));
        const u64 hsB = add2(add2(relu2(c0), relu2(c1)),
                             add2(relu2(c2), relu2(c3)));
        // layer 2 folded through mean; packed W2 pairs, 3 LDC.128 per block
        const float4 w2q0 = cW2q[3 * j + 0];  // (A.o0, A.o1)
        const float4 w2q1 = cW2q[3 * j + 1];  // (A.o2, B.o0)
        const float4 w2q2 = cW2q[3 * j + 2];  // (B.o1, B.o2)
        y0p = fma2(hsA, f4lo(w2q0), y0p);
        y1p = fma2(hsA, f4hi(w2q0), y1p);
        y2p = fma2(hsA, f4lo(w2q1), y2p);
        y0p = fma2(hsB, f4hi(w2q1), y0p);
        y1p = fma2(hsB, f4lo(w2q2), y1p);
        y2p = fma2(hsB, f4hi(w2q2), y2p);
    }

    float e, o;
    unpack2(y0p, e, o); float y0 = e + o;
    unpack2(y1p, e, o); float y1 = e + o;
    unpack2(y2p, e, o); float y2 = e + o;

    // Reduce over the 4 sibling lanes (adjacent lanes: xor 1, then 2).
    #pragma unroll
    for (int d = 1; d < 4; d <<= 1) {
        y0 += __shfl_xor_sync(0xffffffffu, y0, d);
        y1 += __shfl_xor_sync(0xffffffffu, y1, d);
        y2 += __shfl_xor_sync(0xffffffffu, y2, d);
    }

    if (sub < F_OUT) {
        float v = (sub == 0) ? y0 : (sub == 1) ? y1 : y2;
        out[node * F_OUT + sub] = v + cAll[OFF_B2 + sub];
    }
}

extern "C" void kernel_launch(void* const* d_in, const int* in_sizes, int n_in,
                              void* d_out, int out_size) {
    const float* mailbox = (const float*)d_in[0];
    float* out = (float*)d_out;

    // 1) Pack weights into contiguous device staging (kernel node).
    gather_weights<<<1, 512>>>((const float*)d_in[1], (const float*)d_in[2],
                               (const float*)d_in[3], (const float*)d_in[4]);
    // 2) Single D2D copy into constant memory (graph-capturable).
    void* stage_ptr = nullptr;
    cudaGetSymbolAddress(&stage_ptr, g_stage);
    cudaMemcpyToSymbolAsync(cAll, stage_ptr, W_TOTAL * sizeof(float), 0,
                            cudaMemcpyDeviceToDevice, 0);

    const int n_nodes = in_sizes[0] / (KNBR * F_IN);
    const long long total_threads = (long long)n_nodes * 4;
    const int blocks = (int)((total_threads + BLOCK - 1) / BLOCK);

    aggre_mlp_kernel<<<blocks, BLOCK>>>(mailbox, out, n_nodes);
}